// round 2
// baseline (speedup 1.0000x reference)
#include <cuda_runtime.h>

#define N_NODES 100000
#define N_EDGES 1600000

// ---------------- scratch (static device globals; no allocation allowed) ----
__device__ __align__(16) float g_deg [N_NODES];
__device__ __align__(16) float g_dinv[N_NODES];
__device__ __align__(16) float g_norm[N_EDGES];
__device__ __align__(16) float g_h   [N_NODES * 64];  // transformed features (layer 1/2)
__device__ __align__(16) float g_l1  [N_NODES * 64];  // layer-1 output
__device__ __align__(16) float g_l2  [N_NODES * 64];  // layer-2 output
__device__ __align__(16) float g_h3  [N_NODES * 32];  // layer-3 transformed features

// ---------------- degree / norm preparation -------------------------------
__global__ void zero_deg_kernel() {
    int i = blockIdx.x * blockDim.x + threadIdx.x;
    if (i < N_NODES) g_deg[i] = 0.0f;
}

// edge_index is int32 (JAX x64 is disabled by default, so jnp.int64 -> int32)
__global__ void deg_kernel(const int* __restrict__ dst) {
    int e = blockIdx.x * blockDim.x + threadIdx.x;
    if (e < N_EDGES) atomicAdd(&g_deg[dst[e]], 1.0f);
}

__global__ void dinv_kernel() {
    int i = blockIdx.x * blockDim.x + threadIdx.x;
    if (i < N_NODES) g_dinv[i] = rsqrtf(g_deg[i] + 1.0f);  // +1 = self-loop
}

__global__ void norm_kernel(const int* __restrict__ src,
                            const int* __restrict__ dst) {
    int e = blockIdx.x * blockDim.x + threadIdx.x;
    if (e < N_EDGES) g_norm[e] = g_dinv[src[e]] * g_dinv[dst[e]];
}

// ---------------- dense GEMM: H[n, FOUT] = X[n, 64] @ W[64, FOUT] ----------
template <int FOUT>
__global__ void gemm_kernel(const float* __restrict__ X,
                            const float* __restrict__ W,
                            float* __restrict__ H, int n) {
    constexpr int C4  = FOUT / 4;   // float4-columns per row
    constexpr int RPI = 256 / C4;   // rows processed per iteration
    __shared__ float4 Ws[64 * C4];
    for (int i = threadIdx.x; i < 64 * C4; i += 256)
        Ws[i] = ((const float4*)W)[i];
    __syncthreads();

    int c  = threadIdx.x % C4;
    int rl = threadIdx.x / C4;
    int row0 = blockIdx.x * 64;

    for (int rr = rl; rr < 64; rr += RPI) {
        int r = row0 + rr;
        if (r >= n) continue;
        const float4* xr = (const float4*)(X + (size_t)r * 64);
        float4 acc = make_float4(0.f, 0.f, 0.f, 0.f);
#pragma unroll
        for (int k4 = 0; k4 < 16; k4++) {
            float4 xv = xr[k4];
#pragma unroll
            for (int j = 0; j < 4; j++) {
                float xs = (j == 0) ? xv.x : (j == 1) ? xv.y : (j == 2) ? xv.z : xv.w;
                float4 w = Ws[(k4 * 4 + j) * C4 + c];
                acc.x = fmaf(xs, w.x, acc.x);
                acc.y = fmaf(xs, w.y, acc.y);
                acc.z = fmaf(xs, w.z, acc.z);
                acc.w = fmaf(xs, w.w, acc.w);
            }
        }
        ((float4*)(H + (size_t)r * FOUT))[c] = acc;
    }
}

// ---------------- self-loop init: out[i] = dinv[i]^2 * h[i] ----------------
template <int F>
__global__ void self_init_kernel(const float* __restrict__ h,
                                 float* __restrict__ out) {
    constexpr int G = F / 4;
    int tid = blockIdx.x * blockDim.x + threadIdx.x;
    if (tid >= N_NODES * G) return;
    int i = tid / G;
    float s = g_dinv[i];
    s = s * s;
    float4 v = ((const float4*)h)[tid];
    v.x *= s; v.y *= s; v.z *= s; v.w *= s;
    ((float4*)out)[tid] = v;
}

// ---------------- edge aggregation: out[dst] += norm * h[src] --------------
// One thread per (edge, 4-feature group); red.global.add.v4.f32 => E*F/4
// fire-and-forget L2 reductions instead of E*F scalar atomics.
template <int F>
__global__ void edge_agg_kernel(const int* __restrict__ src,
                                const int* __restrict__ dst,
                                const float* __restrict__ h,
                                float* __restrict__ out) {
    constexpr int G = F / 4;
    long long tid = (long long)blockIdx.x * blockDim.x + threadIdx.x;
    int e = (int)(tid / G);
    int g = (int)(tid % G);
    if (e >= N_EDGES) return;
    int s = src[e];
    int d = dst[e];
    float nm = g_norm[e];
    float4 v = ((const float4*)(h + (size_t)s * F))[g];
    v.x *= nm; v.y *= nm; v.z *= nm; v.w *= nm;
    float* p = out + (size_t)d * F + 4 * g;
    asm volatile("red.global.add.v4.f32 [%0], {%1,%2,%3,%4};"
                 :: "l"(p), "f"(v.x), "f"(v.y), "f"(v.z), "f"(v.w)
                 : "memory");
}

// ---------------- bias + optional relu -------------------------------------
template <int F, bool RELU>
__global__ void bias_act_kernel(float* __restrict__ out,
                                const float* __restrict__ b) {
    int tid = blockIdx.x * blockDim.x + threadIdx.x;
    if (tid >= N_NODES * F) return;
    int f = tid % F;
    float v = out[tid] + b[f];
    if (RELU) v = fmaxf(v, 0.0f);
    out[tid] = v;
}

// ---------------- host-side launcher ---------------------------------------
extern "C" void kernel_launch(void* const* d_in, const int* in_sizes, int n_in,
                              void* d_out, int out_size) {
    const float* x   = (const float*)d_in[0];
    const int*   ei  = (const int*)d_in[1];     // int32! (JAX x64 disabled)
    const int*   src = ei;
    const int*   dst = ei + N_EDGES;
    const float* W1  = (const float*)d_in[2];
    const float* b1  = (const float*)d_in[3];
    const float* W2  = (const float*)d_in[4];
    const float* b2  = (const float*)d_in[5];
    const float* W3  = (const float*)d_in[6];
    const float* b3  = (const float*)d_in[7];
    float* out = (float*)d_out;

    void *p_h = nullptr, *p_l1 = nullptr, *p_l2 = nullptr, *p_h3 = nullptr;
    cudaGetSymbolAddress(&p_h,  g_h);
    cudaGetSymbolAddress(&p_l1, g_l1);
    cudaGetSymbolAddress(&p_l2, g_l2);
    cudaGetSymbolAddress(&p_h3, g_h3);
    float* h  = (float*)p_h;
    float* l1 = (float*)p_l1;
    float* l2 = (float*)p_l2;
    float* h3 = (float*)p_h3;

    const int n = N_NODES;
    const int TB = 256;
    const int gN   = (N_NODES + TB - 1) / TB;
    const int gE   = (N_EDGES + TB - 1) / TB;
    const int gGemm = (N_NODES + 63) / 64;
    const int gN16 = (N_NODES * 16 + TB - 1) / TB;   // F=64 float4 groups
    const int gN8  = (N_NODES * 8  + TB - 1) / TB;   // F=32 float4 groups
    const int gE16 = (int)(((long long)N_EDGES * 16 + TB - 1) / TB);
    const int gE8  = (int)(((long long)N_EDGES * 8  + TB - 1) / TB);
    const int gNF64 = (N_NODES * 64 + TB - 1) / TB;
    const int gNF32 = (N_NODES * 32 + TB - 1) / TB;

    // --- prep: degree, dinv, per-edge norm ---
    zero_deg_kernel<<<gN, TB>>>();
    deg_kernel<<<gE, TB>>>(dst);
    dinv_kernel<<<gN, TB>>>();
    norm_kernel<<<gE, TB>>>(src, dst);

    // --- layer 1: 64 -> 64, relu ---
    gemm_kernel<64><<<gGemm, TB>>>(x, W1, h, n);
    self_init_kernel<64><<<gN16, TB>>>(h, l1);
    edge_agg_kernel<64><<<gE16, TB>>>(src, dst, h, l1);
    bias_act_kernel<64, true><<<gNF64, TB>>>(l1, b1);

    // --- layer 2: 64 -> 64, relu ---
    gemm_kernel<64><<<gGemm, TB>>>(l1, W2, h, n);
    self_init_kernel<64><<<gN16, TB>>>(h, l2);
    edge_agg_kernel<64><<<gE16, TB>>>(src, dst, h, l2);
    bias_act_kernel<64, true><<<gNF64, TB>>>(l2, b2);

    // --- layer 3: 64 -> 32, no relu, straight into d_out ---
    gemm_kernel<32><<<gGemm, TB>>>(l2, W3, h3, n);
    self_init_kernel<32><<<gN8, TB>>>(h3, out);
    edge_agg_kernel<32><<<gE8, TB>>>(src, dst, h3, out);
    bias_act_kernel<32, false><<<gNF32, TB>>>(out, b3);
}

// round 3
// speedup vs baseline: 1.3860x; 1.3860x over previous
#include <cuda_runtime.h>

#define N_NODES 100000
#define N_EDGES 1600000
#define NB_SCAN ((N_NODES + 1023) / 1024)   // 98 scan blocks

// ---------------- scratch (static device globals; no allocation allowed) ----
__device__ __align__(16) int   g_cnt [N_NODES];      // in-degree (by dst)
__device__ __align__(16) int   g_off [N_NODES];      // CSR row offsets (exclusive scan)
__device__ __align__(16) int   g_cur [N_NODES];      // scatter cursors (== row end after scatter)
__device__ __align__(16) int   g_bsum[NB_SCAN];
__device__ __align__(16) int   g_bsc [NB_SCAN];
__device__ __align__(16) float g_dinv[N_NODES];
__device__ __align__(16) int2  g_csr [N_EDGES];      // (src, norm-as-int) in CSR order
__device__ __align__(16) float g_h   [N_NODES * 64]; // transformed features (layers 1/2)
__device__ __align__(16) float g_l1  [N_NODES * 64];
__device__ __align__(16) float g_l2  [N_NODES * 64];
__device__ __align__(16) float g_h3  [N_NODES * 32];

// ---------------- CSR construction ------------------------------------------
__global__ void zero_cnt_kernel() {
    int i = blockIdx.x * blockDim.x + threadIdx.x;
    if (i < N_NODES) g_cnt[i] = 0;
}

__global__ void deg_kernel(const int* __restrict__ dst) {
    int e = blockIdx.x * blockDim.x + threadIdx.x;
    if (e < N_EDGES) atomicAdd(&g_cnt[dst[e]], 1);
}

__global__ void dinv_kernel() {
    int i = blockIdx.x * blockDim.x + threadIdx.x;
    if (i < N_NODES) g_dinv[i] = rsqrtf((float)g_cnt[i] + 1.0f);  // +1 self-loop
}

// block-level Hillis-Steele scan (1024 elements per block)
__global__ void scan1_kernel() {
    __shared__ int sh[1024];
    int i = blockIdx.x * 1024 + threadIdx.x;
    int v = (i < N_NODES) ? g_cnt[i] : 0;
    sh[threadIdx.x] = v;
    __syncthreads();
#pragma unroll
    for (int s = 1; s < 1024; s <<= 1) {
        int t = 0;
        if (threadIdx.x >= s) t = sh[threadIdx.x - s];
        __syncthreads();
        if (threadIdx.x >= s) sh[threadIdx.x] += t;
        __syncthreads();
    }
    if (i < N_NODES) g_off[i] = sh[threadIdx.x] - v;   // exclusive within block
    if (threadIdx.x == 1023) g_bsum[blockIdx.x] = sh[1023];
}

__global__ void scan2_kernel() {   // tiny: serial scan of 98 block sums
    if (threadIdx.x == 0) {
        int run = 0;
        for (int b = 0; b < NB_SCAN; b++) {
            g_bsc[b] = run;
            run += g_bsum[b];
        }
    }
}

__global__ void scan3_kernel() {
    int i = blockIdx.x * blockDim.x + threadIdx.x;
    if (i < N_NODES) {
        int o = g_off[i] + g_bsc[i >> 10];
        g_off[i] = o;
        g_cur[i] = o;   // reset cursors (graph-replay safe)
    }
}

// scatter edges into CSR order; compute norm on the fly
__global__ void scatter_kernel(const int* __restrict__ src,
                               const int* __restrict__ dst) {
    int e = blockIdx.x * blockDim.x + threadIdx.x;
    if (e >= N_EDGES) return;
    int s = src[e];
    int d = dst[e];
    float nm = g_dinv[s] * g_dinv[d];
    int pos = atomicAdd(&g_cur[d], 1);
    g_csr[pos] = make_int2(s, __float_as_int(nm));
}

// ---------------- dense GEMM: H[n, FOUT] = X[n, 64] @ W[64, FOUT] -----------
template <int FOUT>
__global__ void gemm_kernel(const float* __restrict__ X,
                            const float* __restrict__ W,
                            float* __restrict__ H, int n) {
    constexpr int C4  = FOUT / 4;
    constexpr int RPI = 256 / C4;
    __shared__ float4 Ws[64 * C4];
    for (int i = threadIdx.x; i < 64 * C4; i += 256)
        Ws[i] = ((const float4*)W)[i];
    __syncthreads();

    int c  = threadIdx.x % C4;
    int rl = threadIdx.x / C4;
    int row0 = blockIdx.x * 64;

    for (int rr = rl; rr < 64; rr += RPI) {
        int r = row0 + rr;
        if (r >= n) continue;
        const float4* xr = (const float4*)(X + (size_t)r * 64);
        float4 acc = make_float4(0.f, 0.f, 0.f, 0.f);
#pragma unroll
        for (int k4 = 0; k4 < 16; k4++) {
            float4 xv = xr[k4];
#pragma unroll
            for (int j = 0; j < 4; j++) {
                float xs = (j == 0) ? xv.x : (j == 1) ? xv.y : (j == 2) ? xv.z : xv.w;
                float4 w = Ws[(k4 * 4 + j) * C4 + c];
                acc.x = fmaf(xs, w.x, acc.x);
                acc.y = fmaf(xs, w.y, acc.y);
                acc.z = fmaf(xs, w.z, acc.z);
                acc.w = fmaf(xs, w.w, acc.w);
            }
        }
        ((float4*)(H + (size_t)r * FOUT))[c] = acc;
    }
}

// ---------------- fused aggregation: warp per node --------------------------
// out[node] = [relu]( dinv^2*h[node] + sum_in norm*h[src] + bias )
// No atomics. Gathers are coalesced full rows (F*4 bytes per edge).
template <int F, bool RELU>
__global__ void __launch_bounds__(256) agg_kernel(const float* __restrict__ h,
                                                  const float* __restrict__ bias,
                                                  float* __restrict__ out) {
    int node = (blockIdx.x * 256 + threadIdx.x) >> 5;
    int lane = threadIdx.x & 31;
    if (node >= N_NODES) return;

    float dv  = g_dinv[node];
    float s2  = dv * dv;
    int   beg = g_off[node];
    int   end = g_cur[node];   // == row end after scatter

    if constexpr (F == 64) {
        const float2* hb = (const float2*)h;
        float2 acc = hb[(size_t)node * 32 + lane];
        acc.x *= s2; acc.y *= s2;
        int i = beg;
        for (; i + 4 <= end; i += 4) {
            int2 e0 = g_csr[i], e1 = g_csr[i + 1], e2 = g_csr[i + 2], e3 = g_csr[i + 3];
            float2 v0 = hb[(size_t)e0.x * 32 + lane];
            float2 v1 = hb[(size_t)e1.x * 32 + lane];
            float2 v2 = hb[(size_t)e2.x * 32 + lane];
            float2 v3 = hb[(size_t)e3.x * 32 + lane];
            float n0 = __int_as_float(e0.y), n1 = __int_as_float(e1.y);
            float n2 = __int_as_float(e2.y), n3 = __int_as_float(e3.y);
            acc.x = fmaf(n0, v0.x, acc.x); acc.y = fmaf(n0, v0.y, acc.y);
            acc.x = fmaf(n1, v1.x, acc.x); acc.y = fmaf(n1, v1.y, acc.y);
            acc.x = fmaf(n2, v2.x, acc.x); acc.y = fmaf(n2, v2.y, acc.y);
            acc.x = fmaf(n3, v3.x, acc.x); acc.y = fmaf(n3, v3.y, acc.y);
        }
        for (; i < end; i++) {
            int2 e0 = g_csr[i];
            float2 v0 = hb[(size_t)e0.x * 32 + lane];
            float n0 = __int_as_float(e0.y);
            acc.x = fmaf(n0, v0.x, acc.x); acc.y = fmaf(n0, v0.y, acc.y);
        }
        float2 bb = ((const float2*)bias)[lane];
        acc.x += bb.x; acc.y += bb.y;
        if (RELU) { acc.x = fmaxf(acc.x, 0.f); acc.y = fmaxf(acc.y, 0.f); }
        ((float2*)out)[(size_t)node * 32 + lane] = acc;
    } else {  // F == 32: one float per lane
        float acc = h[(size_t)node * 32 + lane] * s2;
        int i = beg;
        for (; i + 4 <= end; i += 4) {
            int2 e0 = g_csr[i], e1 = g_csr[i + 1], e2 = g_csr[i + 2], e3 = g_csr[i + 3];
            float v0 = h[(size_t)e0.x * 32 + lane];
            float v1 = h[(size_t)e1.x * 32 + lane];
            float v2 = h[(size_t)e2.x * 32 + lane];
            float v3 = h[(size_t)e3.x * 32 + lane];
            acc = fmaf(__int_as_float(e0.y), v0, acc);
            acc = fmaf(__int_as_float(e1.y), v1, acc);
            acc = fmaf(__int_as_float(e2.y), v2, acc);
            acc = fmaf(__int_as_float(e3.y), v3, acc);
        }
        for (; i < end; i++) {
            int2 e0 = g_csr[i];
            acc = fmaf(__int_as_float(e0.y), h[(size_t)e0.x * 32 + lane], acc);
        }
        acc += bias[lane];
        if (RELU) acc = fmaxf(acc, 0.f);
        out[(size_t)node * 32 + lane] = acc;
    }
}

// ---------------- host-side launcher ---------------------------------------
extern "C" void kernel_launch(void* const* d_in, const int* in_sizes, int n_in,
                              void* d_out, int out_size) {
    const float* x   = (const float*)d_in[0];
    const int*   ei  = (const int*)d_in[1];     // int32 (JAX x64 disabled)
    const int*   src = ei;
    const int*   dst = ei + N_EDGES;
    const float* W1  = (const float*)d_in[2];
    const float* b1  = (const float*)d_in[3];
    const float* W2  = (const float*)d_in[4];
    const float* b2  = (const float*)d_in[5];
    const float* W3  = (const float*)d_in[6];
    const float* b3  = (const float*)d_in[7];
    float* out = (float*)d_out;

    void *p_h, *p_l1, *p_l2, *p_h3;
    cudaGetSymbolAddress(&p_h,  g_h);
    cudaGetSymbolAddress(&p_l1, g_l1);
    cudaGetSymbolAddress(&p_l2, g_l2);
    cudaGetSymbolAddress(&p_h3, g_h3);
    float* h  = (float*)p_h;
    float* l1 = (float*)p_l1;
    float* l2 = (float*)p_l2;
    float* h3 = (float*)p_h3;

    const int n  = N_NODES;
    const int TB = 256;
    const int gN = (N_NODES + TB - 1) / TB;
    const int gE = (N_EDGES + TB - 1) / TB;
    const int gGemm = (N_NODES + 63) / 64;
    const int gAgg  = (N_NODES * 32 + TB - 1) / TB;   // warp per node

    // --- CSR build (per launch; graph-replay idempotent) ---
    zero_cnt_kernel<<<gN, TB>>>();
    deg_kernel<<<gE, TB>>>(dst);
    dinv_kernel<<<gN, TB>>>();
    scan1_kernel<<<NB_SCAN, 1024>>>();
    scan2_kernel<<<1, 32>>>();
    scan3_kernel<<<gN, TB>>>();
    scatter_kernel<<<gE, TB>>>(src, dst);

    // --- layer 1: 64 -> 64, relu ---
    gemm_kernel<64><<<gGemm, TB>>>(x, W1, h, n);
    agg_kernel<64, true><<<gAgg, TB>>>(h, b1, l1);

    // --- layer 2: 64 -> 64, relu ---
    gemm_kernel<64><<<gGemm, TB>>>(l1, W2, h, n);
    agg_kernel<64, true><<<gAgg, TB>>>(h, b2, l2);

    // --- layer 3: 64 -> 32, no relu ---
    gemm_kernel<32><<<gGemm, TB>>>(l2, W3, h3, n);
    agg_kernel<32, false><<<gAgg, TB>>>(h3, b3, out);
}

// round 4
// speedup vs baseline: 1.4468x; 1.0439x over previous
#include <cuda_runtime.h>
#include <cuda_fp16.h>

#define N_NODES 100000
#define N_EDGES 1600000
#define NB_SCAN ((N_NODES + 1023) / 1024)   // 98 scan blocks

// ---------------- scratch (static device globals; no allocation allowed) ----
__device__ __align__(16) int    g_cnt [N_NODES];
__device__ __align__(16) int    g_off [N_NODES];
__device__ __align__(16) int    g_cur [N_NODES];
__device__ __align__(16) int    g_bsum[NB_SCAN];
__device__ __align__(16) int    g_bsc [NB_SCAN];
__device__ __align__(16) float  g_dinv[N_NODES];
__device__ __align__(16) int    g_csr [N_EDGES];       // src only, CSR-by-dst order
__device__ __align__(16) __half g_h   [N_NODES * 64];  // fp16 transformed features
__device__ __align__(16) __half g_h3  [N_NODES * 32];
__device__ __align__(16) float  g_l1  [N_NODES * 64];
__device__ __align__(16) float  g_l2  [N_NODES * 64];

// ---------------- CSR construction ------------------------------------------
__global__ void zero_cnt_kernel() {
    int i = blockIdx.x * blockDim.x + threadIdx.x;
    if (i < N_NODES) g_cnt[i] = 0;
}

__global__ void deg_kernel(const int* __restrict__ dst) {
    int e = blockIdx.x * blockDim.x + threadIdx.x;
    if (e < N_EDGES) atomicAdd(&g_cnt[dst[e]], 1);
}

__global__ void dinv_kernel() {
    int i = blockIdx.x * blockDim.x + threadIdx.x;
    if (i < N_NODES) g_dinv[i] = rsqrtf((float)g_cnt[i] + 1.0f);  // +1 self-loop
}

__global__ void scan1_kernel() {
    __shared__ int sh[1024];
    int i = blockIdx.x * 1024 + threadIdx.x;
    int v = (i < N_NODES) ? g_cnt[i] : 0;
    sh[threadIdx.x] = v;
    __syncthreads();
#pragma unroll
    for (int s = 1; s < 1024; s <<= 1) {
        int t = 0;
        if (threadIdx.x >= s) t = sh[threadIdx.x - s];
        __syncthreads();
        if (threadIdx.x >= s) sh[threadIdx.x] += t;
        __syncthreads();
    }
    if (i < N_NODES) g_off[i] = sh[threadIdx.x] - v;
    if (threadIdx.x == 1023) g_bsum[blockIdx.x] = sh[1023];
}

__global__ void scan2_kernel() {   // parallel scan of NB_SCAN block sums
    __shared__ int sh[128];
    int t = threadIdx.x;
    int v = (t < NB_SCAN) ? g_bsum[t] : 0;
    sh[t] = v;
    __syncthreads();
#pragma unroll
    for (int s = 1; s < 128; s <<= 1) {
        int u = 0;
        if (t >= s) u = sh[t - s];
        __syncthreads();
        if (t >= s) sh[t] += u;
        __syncthreads();
    }
    if (t < NB_SCAN) g_bsc[t] = sh[t] - v;   // exclusive
}

__global__ void scan3_kernel() {
    int i = blockIdx.x * blockDim.x + threadIdx.x;
    if (i < N_NODES) {
        int o = g_off[i] + g_bsc[i >> 10];
        g_off[i] = o;
        g_cur[i] = o;
    }
}

__global__ void scatter_kernel(const int* __restrict__ src,
                               const int* __restrict__ dst) {
    int e = blockIdx.x * blockDim.x + threadIdx.x;
    if (e >= N_EDGES) return;
    int pos = atomicAdd(&g_cur[dst[e]], 1);
    g_csr[pos] = src[e];
}

// ---------------- dense GEMM: H[n, FOUT](fp16) = X[n, 64](fp32) @ W ---------
template <int FOUT>
__global__ void gemm_kernel(const float* __restrict__ X,
                            const float* __restrict__ W,
                            __half* __restrict__ H, int n) {
    constexpr int C4  = FOUT / 4;
    constexpr int RPI = 256 / C4;
    __shared__ float4 Ws[64 * C4];
    for (int i = threadIdx.x; i < 64 * C4; i += 256)
        Ws[i] = ((const float4*)W)[i];
    __syncthreads();

    int c  = threadIdx.x % C4;
    int rl = threadIdx.x / C4;
    int row0 = blockIdx.x * 64;

    for (int rr = rl; rr < 64; rr += RPI) {
        int r = row0 + rr;
        if (r >= n) continue;
        const float4* xr = (const float4*)(X + (size_t)r * 64);
        float4 acc = make_float4(0.f, 0.f, 0.f, 0.f);
#pragma unroll
        for (int k4 = 0; k4 < 16; k4++) {
            float4 xv = xr[k4];
#pragma unroll
            for (int j = 0; j < 4; j++) {
                float xs = (j == 0) ? xv.x : (j == 1) ? xv.y : (j == 2) ? xv.z : xv.w;
                float4 w = Ws[(k4 * 4 + j) * C4 + c];
                acc.x = fmaf(xs, w.x, acc.x);
                acc.y = fmaf(xs, w.y, acc.y);
                acc.z = fmaf(xs, w.z, acc.z);
                acc.w = fmaf(xs, w.w, acc.w);
            }
        }
        half2 h0 = __floats2half2_rn(acc.x, acc.y);
        half2 h1 = __floats2half2_rn(acc.z, acc.w);
        ((half2*)(H + (size_t)r * FOUT))[2 * c]     = h0;
        ((half2*)(H + (size_t)r * FOUT))[2 * c + 1] = h1;
    }
}

// ---------------- fused aggregation: warp per node --------------------------
// out[node] = [relu]( dinv^2*h[node] + sum_in dinv[s]*dinv[node]*h[s] + bias )
// fp16 gathers, fp32 accumulation; norm recomputed from L2-resident dinv.
template <int F, bool RELU>
__global__ void __launch_bounds__(256) agg_kernel(const __half* __restrict__ h,
                                                  const float* __restrict__ bias,
                                                  float* __restrict__ out) {
    int node = (blockIdx.x * 256 + threadIdx.x) >> 5;
    int lane = threadIdx.x & 31;
    if (node >= N_NODES) return;

    float dv  = g_dinv[node];
    int   beg = g_off[node];
    int   end = g_cur[node];

    if constexpr (F == 64) {
        const half2* hb = (const half2*)h;
        float2 self = __half22float2(hb[(size_t)node * 32 + lane]);
        float2 acc;
        acc.x = self.x * dv * dv;
        acc.y = self.y * dv * dv;
        int i = beg;
        for (; i + 4 <= end; i += 4) {
            int s0 = g_csr[i], s1 = g_csr[i + 1], s2 = g_csr[i + 2], s3 = g_csr[i + 3];
            float n0 = g_dinv[s0] * dv, n1 = g_dinv[s1] * dv;
            float n2 = g_dinv[s2] * dv, n3 = g_dinv[s3] * dv;
            float2 v0 = __half22float2(hb[(size_t)s0 * 32 + lane]);
            float2 v1 = __half22float2(hb[(size_t)s1 * 32 + lane]);
            float2 v2 = __half22float2(hb[(size_t)s2 * 32 + lane]);
            float2 v3 = __half22float2(hb[(size_t)s3 * 32 + lane]);
            acc.x = fmaf(n0, v0.x, acc.x); acc.y = fmaf(n0, v0.y, acc.y);
            acc.x = fmaf(n1, v1.x, acc.x); acc.y = fmaf(n1, v1.y, acc.y);
            acc.x = fmaf(n2, v2.x, acc.x); acc.y = fmaf(n2, v2.y, acc.y);
            acc.x = fmaf(n3, v3.x, acc.x); acc.y = fmaf(n3, v3.y, acc.y);
        }
        for (; i < end; i++) {
            int s0 = g_csr[i];
            float n0 = g_dinv[s0] * dv;
            float2 v0 = __half22float2(hb[(size_t)s0 * 32 + lane]);
            acc.x = fmaf(n0, v0.x, acc.x); acc.y = fmaf(n0, v0.y, acc.y);
        }
        float2 bb = ((const float2*)bias)[lane];
        acc.x += bb.x; acc.y += bb.y;
        if (RELU) { acc.x = fmaxf(acc.x, 0.f); acc.y = fmaxf(acc.y, 0.f); }
        ((float2*)out)[(size_t)node * 32 + lane] = acc;
    } else {  // F == 32: one half per lane
        float acc = __half2float(h[(size_t)node * 32 + lane]) * dv * dv;
        int i = beg;
        for (; i + 4 <= end; i += 4) {
            int s0 = g_csr[i], s1 = g_csr[i + 1], s2 = g_csr[i + 2], s3 = g_csr[i + 3];
            float n0 = g_dinv[s0] * dv, n1 = g_dinv[s1] * dv;
            float n2 = g_dinv[s2] * dv, n3 = g_dinv[s3] * dv;
            float v0 = __half2float(h[(size_t)s0 * 32 + lane]);
            float v1 = __half2float(h[(size_t)s1 * 32 + lane]);
            float v2 = __half2float(h[(size_t)s2 * 32 + lane]);
            float v3 = __half2float(h[(size_t)s3 * 32 + lane]);
            acc = fmaf(n0, v0, acc);
            acc = fmaf(n1, v1, acc);
            acc = fmaf(n2, v2, acc);
            acc = fmaf(n3, v3, acc);
        }
        for (; i < end; i++) {
            int s0 = g_csr[i];
            acc = fmaf(g_dinv[s0] * dv, __half2float(h[(size_t)s0 * 32 + lane]), acc);
        }
        acc += bias[lane];
        if (RELU) acc = fmaxf(acc, 0.f);
        out[(size_t)node * 32 + lane] = acc;
    }
}

// ---------------- host-side launcher ---------------------------------------
extern "C" void kernel_launch(void* const* d_in, const int* in_sizes, int n_in,
                              void* d_out, int out_size) {
    const float* x   = (const float*)d_in[0];
    const int*   ei  = (const int*)d_in[1];     // int32 (JAX x64 disabled)
    const int*   src = ei;
    const int*   dst = ei + N_EDGES;
    const float* W1  = (const float*)d_in[2];
    const float* b1  = (const float*)d_in[3];
    const float* W2  = (const float*)d_in[4];
    const float* b2  = (const float*)d_in[5];
    const float* W3  = (const float*)d_in[6];
    const float* b3  = (const float*)d_in[7];
    float* out = (float*)d_out;

    void *p_h, *p_l1, *p_l2, *p_h3;
    cudaGetSymbolAddress(&p_h,  g_h);
    cudaGetSymbolAddress(&p_l1, g_l1);
    cudaGetSymbolAddress(&p_l2, g_l2);
    cudaGetSymbolAddress(&p_h3, g_h3);
    __half* h  = (__half*)p_h;
    float*  l1 = (float*)p_l1;
    float*  l2 = (float*)p_l2;
    __half* h3 = (__half*)p_h3;

    const int n  = N_NODES;
    const int TB = 256;
    const int gN = (N_NODES + TB - 1) / TB;
    const int gE = (N_EDGES + TB - 1) / TB;
    const int gGemm = (N_NODES + 63) / 64;
    const int gAgg  = (N_NODES * 32 + TB - 1) / TB;

    // --- CSR build ---
    zero_cnt_kernel<<<gN, TB>>>();
    deg_kernel<<<gE, TB>>>(dst);
    dinv_kernel<<<gN, TB>>>();
    scan1_kernel<<<NB_SCAN, 1024>>>();
    scan2_kernel<<<1, 128>>>();
    scan3_kernel<<<gN, TB>>>();
    scatter_kernel<<<gE, TB>>>(src, dst);

    // --- layer 1: 64 -> 64, relu ---
    gemm_kernel<64><<<gGemm, TB>>>(x, W1, h, n);
    agg_kernel<64, true><<<gAgg, TB>>>(h, b1, l1);

    // --- layer 2: 64 -> 64, relu ---
    gemm_kernel<64><<<gGemm, TB>>>(l1, W2, h, n);
    agg_kernel<64, true><<<gAgg, TB>>>(h, b2, l2);

    // --- layer 3: 64 -> 32, no relu ---
    gemm_kernel<32><<<gGemm, TB>>>(l2, W3, h3, n);
    agg_kernel<32, false><<<gAgg, TB>>>(h3, b3, out);
}

// round 5
// speedup vs baseline: 1.4482x; 1.0009x over previous
#include <cuda_runtime.h>
#include <cuda_fp16.h>

#define N_NODES 100000
#define N_EDGES 1600000
#define NB_SCAN ((N_NODES + 1023) / 1024)   // 98 scan blocks

// ---------------- scratch (static device globals; no allocation allowed) ----
__device__ __align__(16) int    g_cnt [N_NODES];
__device__ __align__(16) int    g_off [N_NODES];
__device__ __align__(16) int    g_cur [N_NODES];
__device__ __align__(16) int    g_bsum[NB_SCAN];
__device__ __align__(16) float  g_dinv[N_NODES];
__device__ __align__(16) int2   g_csr [N_EDGES];       // (src, norm) CSR-by-dst
__device__ __align__(16) __half g_h   [N_NODES * 64];  // fp16 transformed features
__device__ __align__(16) __half g_h3  [N_NODES * 32];
__device__ __align__(16) float  g_l1  [N_NODES * 64];
__device__ __align__(16) float  g_l2  [N_NODES * 64];

// ---------------- CSR construction ------------------------------------------
__global__ void zero_cnt_kernel() {
    int i = blockIdx.x * blockDim.x + threadIdx.x;
    if (i < N_NODES) g_cnt[i] = 0;
}

__global__ void deg_kernel(const int* __restrict__ dst) {
    int e = blockIdx.x * blockDim.x + threadIdx.x;
    if (e < N_EDGES) atomicAdd(&g_cnt[dst[e]], 1);
}

// block scan of degrees; also computes dinv (fused, reads cnt anyway)
__global__ void scan1_kernel() {
    __shared__ int sh[1024];
    int i = blockIdx.x * 1024 + threadIdx.x;
    int v = (i < N_NODES) ? g_cnt[i] : 0;
    if (i < N_NODES) g_dinv[i] = rsqrtf((float)v + 1.0f);  // +1 self-loop
    sh[threadIdx.x] = v;
    __syncthreads();
#pragma unroll
    for (int s = 1; s < 1024; s <<= 1) {
        int t = 0;
        if (threadIdx.x >= s) t = sh[threadIdx.x - s];
        __syncthreads();
        if (threadIdx.x >= s) sh[threadIdx.x] += t;
        __syncthreads();
    }
    if (i < N_NODES) g_off[i] = sh[threadIdx.x] - v;
    if (threadIdx.x == 1023) g_bsum[blockIdx.x] = sh[1023];
}

// add block-sum prefix (computed inline: <=98 serial L1 reads by thread 0)
__global__ void scan3_kernel() {
    __shared__ int base_sh;
    int nb = (blockIdx.x * 256) >> 10;   // constant within block (256 | 1024)
    if (threadIdx.x == 0) {
        int run = 0;
        for (int k = 0; k < nb; k++) run += g_bsum[k];
        base_sh = run;
    }
    __syncthreads();
    int i = blockIdx.x * 256 + threadIdx.x;
    if (i < N_NODES) {
        int o = g_off[i] + base_sh;
        g_off[i] = o;
        g_cur[i] = o;
    }
}

// scatter edges into CSR order with precomputed norm
__global__ void scatter_kernel(const int* __restrict__ src,
                               const int* __restrict__ dst) {
    int e = blockIdx.x * blockDim.x + threadIdx.x;
    if (e >= N_EDGES) return;
    int s = src[e];
    int d = dst[e];
    float nm = g_dinv[s] * g_dinv[d];
    int pos = atomicAdd(&g_cur[d], 1);
    g_csr[pos] = make_int2(s, __float_as_int(nm));
}

// ---------------- dense GEMM: H[n, FOUT](fp16) = X[n, 64](fp32) @ W ---------
template <int FOUT>
__global__ void gemm_kernel(const float* __restrict__ X,
                            const float* __restrict__ W,
                            __half* __restrict__ H, int n) {
    constexpr int C4  = FOUT / 4;
    constexpr int RPI = 256 / C4;
    __shared__ float4 Ws[64 * C4];
    for (int i = threadIdx.x; i < 64 * C4; i += 256)
        Ws[i] = ((const float4*)W)[i];
    __syncthreads();

    int c  = threadIdx.x % C4;
    int rl = threadIdx.x / C4;
    int row0 = blockIdx.x * 64;

    for (int rr = rl; rr < 64; rr += RPI) {
        int r = row0 + rr;
        if (r >= n) continue;
        const float4* xr = (const float4*)(X + (size_t)r * 64);
        float4 acc = make_float4(0.f, 0.f, 0.f, 0.f);
#pragma unroll
        for (int k4 = 0; k4 < 16; k4++) {
            float4 xv = xr[k4];
#pragma unroll
            for (int j = 0; j < 4; j++) {
                float xs = (j == 0) ? xv.x : (j == 1) ? xv.y : (j == 2) ? xv.z : xv.w;
                float4 w = Ws[(k4 * 4 + j) * C4 + c];
                acc.x = fmaf(xs, w.x, acc.x);
                acc.y = fmaf(xs, w.y, acc.y);
                acc.z = fmaf(xs, w.z, acc.z);
                acc.w = fmaf(xs, w.w, acc.w);
            }
        }
        half2 h0 = __floats2half2_rn(acc.x, acc.y);
        half2 h1 = __floats2half2_rn(acc.z, acc.w);
        ((half2*)(H + (size_t)r * FOUT))[2 * c]     = h0;
        ((half2*)(H + (size_t)r * FOUT))[2 * c + 1] = h1;
    }
}

// ---------------- fused aggregation: warp per node, unroll 8 -----------------
// out[node] = [relu]( dinv^2*h[node] + sum_in norm*h[src] + bias )
// All 8 feature gathers issued back-to-back before any FMA -> MLP ~8.
template <int F, bool RELU>
__global__ void __launch_bounds__(256) agg_kernel(const __half* __restrict__ h,
                                                  const float* __restrict__ bias,
                                                  float* __restrict__ out) {
    int node = (blockIdx.x * 256 + threadIdx.x) >> 5;
    int lane = threadIdx.x & 31;
    if (node >= N_NODES) return;

    float dv  = g_dinv[node];
    float s2  = dv * dv;
    int   beg = g_off[node];
    int   end = g_cur[node];

    if constexpr (F == 64) {
        const half2* hb = (const half2*)h;
        float2 self = __half22float2(hb[(size_t)node * 32 + lane]);
        float2 acc;
        acc.x = self.x * s2;
        acc.y = self.y * s2;
        int i = beg;
        for (; i + 8 <= end; i += 8) {
            int2 e[8];
#pragma unroll
            for (int j = 0; j < 8; j++) e[j] = g_csr[i + j];
            float2 v[8];
#pragma unroll
            for (int j = 0; j < 8; j++)
                v[j] = __half22float2(hb[(size_t)e[j].x * 32 + lane]);
#pragma unroll
            for (int j = 0; j < 8; j++) {
                float nm = __int_as_float(e[j].y);
                acc.x = fmaf(nm, v[j].x, acc.x);
                acc.y = fmaf(nm, v[j].y, acc.y);
            }
        }
        for (; i < end; i++) {
            int2 e0 = g_csr[i];
            float2 v0 = __half22float2(hb[(size_t)e0.x * 32 + lane]);
            float nm = __int_as_float(e0.y);
            acc.x = fmaf(nm, v0.x, acc.x);
            acc.y = fmaf(nm, v0.y, acc.y);
        }
        float2 bb = ((const float2*)bias)[lane];
        acc.x += bb.x; acc.y += bb.y;
        if (RELU) { acc.x = fmaxf(acc.x, 0.f); acc.y = fmaxf(acc.y, 0.f); }
        ((float2*)out)[(size_t)node * 32 + lane] = acc;
    } else {  // F == 32: one half per lane
        float acc = __half2float(h[(size_t)node * 32 + lane]) * s2;
        int i = beg;
        for (; i + 8 <= end; i += 8) {
            int2 e[8];
#pragma unroll
            for (int j = 0; j < 8; j++) e[j] = g_csr[i + j];
            float v[8];
#pragma unroll
            for (int j = 0; j < 8; j++)
                v[j] = __half2float(h[(size_t)e[j].x * 32 + lane]);
#pragma unroll
            for (int j = 0; j < 8; j++)
                acc = fmaf(__int_as_float(e[j].y), v[j], acc);
        }
        for (; i < end; i++) {
            int2 e0 = g_csr[i];
            acc = fmaf(__int_as_float(e0.y),
                       __half2float(h[(size_t)e0.x * 32 + lane]), acc);
        }
        acc += bias[lane];
        if (RELU) acc = fmaxf(acc, 0.f);
        out[(size_t)node * 32 + lane] = acc;
    }
}

// ---------------- host-side launcher ---------------------------------------
extern "C" void kernel_launch(void* const* d_in, const int* in_sizes, int n_in,
                              void* d_out, int out_size) {
    const float* x   = (const float*)d_in[0];
    const int*   ei  = (const int*)d_in[1];     // int32 (JAX x64 disabled)
    const int*   src = ei;
    const int*   dst = ei + N_EDGES;
    const float* W1  = (const float*)d_in[2];
    const float* b1  = (const float*)d_in[3];
    const float* W2  = (const float*)d_in[4];
    const float* b2  = (const float*)d_in[5];
    const float* W3  = (const float*)d_in[6];
    const float* b3  = (const float*)d_in[7];
    float* out = (float*)d_out;

    void *p_h, *p_l1, *p_l2, *p_h3;
    cudaGetSymbolAddress(&p_h,  g_h);
    cudaGetSymbolAddress(&p_l1, g_l1);
    cudaGetSymbolAddress(&p_l2, g_l2);
    cudaGetSymbolAddress(&p_h3, g_h3);
    __half* h  = (__half*)p_h;
    float*  l1 = (float*)p_l1;
    float*  l2 = (float*)p_l2;
    __half* h3 = (__half*)p_h3;

    const int n  = N_NODES;
    const int TB = 256;
    const int gN = (N_NODES + TB - 1) / TB;
    const int gE = (N_EDGES + TB - 1) / TB;
    const int gGemm = (N_NODES + 63) / 64;
    const int gAgg  = (N_NODES * 32 + TB - 1) / TB;

    // --- CSR build (5 launches) ---
    zero_cnt_kernel<<<gN, TB>>>();
    deg_kernel<<<gE, TB>>>(dst);
    scan1_kernel<<<NB_SCAN, 1024>>>();
    scan3_kernel<<<gN, TB>>>();
    scatter_kernel<<<gE, TB>>>(src, dst);

    // --- layer 1: 64 -> 64, relu ---
    gemm_kernel<64><<<gGemm, TB>>>(x, W1, h, n);
    agg_kernel<64, true><<<gAgg, TB>>>(h, b1, l1);

    // --- layer 2: 64 -> 64, relu ---
    gemm_kernel<64><<<gGemm, TB>>>(l1, W2, h, n);
    agg_kernel<64, true><<<gAgg, TB>>>(h, b2, l2);

    // --- layer 3: 64 -> 32, no relu ---
    gemm_kernel<32><<<gGemm, TB>>>(l2, W3, h3, n);
    agg_kernel<32, false><<<gAgg, TB>>>(h3, b3, out);
}